// round 8
// baseline (speedup 1.0000x reference)
#include <cuda_runtime.h>

// S4/DPLR kernel materialization, H=256, N2=64, RANK=1, CH=1, L=2048.
// T=8 blocked rank-1 Woodbury recurrence, linear recombination.
// This round: 2 warps per head on 2 SMSPs. Warp A (role 0) owns the serial
// state chain: mu-dots, mu-rowsum, rank-8 update; publishes (X_l, mu_l) to
// smem. Warp B (role 1) runs one block behind: kappa-dots on X_{l-1}, conv
// with mu_{l-1}, stores. One __syncthreads per block, double buffering.

#define T 8
#define ROWP 36

typedef unsigned long long u64;

__device__ __forceinline__ float wsum(float v) {
    #pragma unroll
    for (int o = 16; o; o >>= 1) v += __shfl_xor_sync(0xffffffffu, v, o);
    return v;
}
__device__ __forceinline__ u64 pk(float x, float y) {
    u64 r; asm("mov.b64 %0,{%1,%2};" : "=l"(r) : "f"(x), "f"(y)); return r;
}
__device__ __forceinline__ float2 up(u64 a) {
    float2 v; asm("mov.b64 {%0,%1},%2;" : "=f"(v.x), "=f"(v.y) : "l"(a)); return v;
}
__device__ __forceinline__ u64 f2fma(u64 a, u64 b, u64 c) {
    u64 d; asm("fma.rn.f32x2 %0,%1,%2,%3;" : "=l"(d) : "l"(a), "l"(b), "l"(c)); return d;
}
__device__ __forceinline__ u64 f2mul(u64 a, u64 b) {
    u64 d; asm("mul.rn.f32x2 %0,%1,%2;" : "=l"(d) : "l"(a), "l"(b)); return d;
}
__device__ __forceinline__ u64 f2add(u64 a, u64 b) {
    u64 d; asm("add.rn.f32x2 %0,%1,%2;" : "=l"(d) : "l"(a), "l"(b)); return d;
}

__global__ __launch_bounds__(128, 1) void ssm_dplr_kernel(
    const float* __restrict__ Ar, const float* __restrict__ Ai,
    const float* __restrict__ Br, const float* __restrict__ Bi,
    const float* __restrict__ Pr, const float* __restrict__ Pi,
    const float* __restrict__ Cr, const float* __restrict__ Ci,
    const float* __restrict__ logdt,
    float* __restrict__ out, int H, int L)
{
    // per-head (2 heads per CTA) buffers
    __shared__ __align__(16) float s_mu_part[2][16 * ROWP];
    __shared__ __align__(16) float s_k_part[2][8 * ROWP];
    __shared__ __align__(16) float s_mu[2][2][16];   // [head][parity][mur0-7,mui0-7]
    __shared__ __align__(16) float s_x[2][2][128];   // [head][parity][lane*4: xr0,xr1,xi0,xi1]

    const int warp = threadIdx.x >> 5;
    const int hloc = warp >> 1;          // head within CTA
    const int role = warp & 1;           // 0 = state warp, 1 = output warp
    const int lane = threadIdx.x & 31;
    const int h = blockIdx.x * 2 + hloc;
    if (h >= H) return;
    const int base = h * 64 + lane;

    const float dt  = expf(logdt[h]);
    const float del = 0.5f * dt;

    // ---- identical setup on both warps of the head ----
    float er[2], ei[2], qr[2], qi[2], ur_[2], ui_[2], c2r[2], c2i[2];
    float pr[2], pi[2], d_r[2], d_i[2];
    float mmr[2], mmi[2];

    float red4[4];
    red4[0] = red4[1] = red4[2] = red4[3] = 0.f;
    #pragma unroll
    for (int s = 0; s < 2; ++s) {
        const int n = base + 32 * s;
        const float lr = -Ar[n], li = -Ai[n];
        const float ar = 1.f + del * lr, ai = del * li;
        const float mr = 1.f - del * lr, mi = -del * li;
        const float idm = 1.f / (mr * mr + mi * mi);
        d_r[s] = mr * idm; d_i[s] = -mi * idm;
        pr[s] = Pr[n]; pi[s] = Pi[n];
        er[s] = d_r[s] * ar - d_i[s] * ai;  ei[s] = d_r[s] * ai + d_i[s] * ar;
        qr[s] = d_r[s] * pr[s] - d_i[s] * pi[s];
        qi[s] = d_r[s] * pi[s] + d_i[s] * pr[s];
        c2r[s] = 2.f * Cr[n]; c2i[s] = 2.f * Ci[n];
        const float pp = pr[s] * pr[s] + pi[s] * pi[s];
        red4[0] += d_r[s] * pp; red4[1] += d_i[s] * pp;
        const float zr = dt * Br[n], zi = dt * Bi[n];
        mmr[s] = d_r[s] * zr - d_i[s] * zi;
        mmi[s] = d_r[s] * zi + d_i[s] * zr;
        red4[2] += pr[s] * mmr[s] + pi[s] * mmi[s];
        red4[3] += pr[s] * mmi[s] - pi[s] * mmr[s];
    }
    #pragma unroll
    for (int o = 16; o; o >>= 1)
        #pragma unroll
        for (int k = 0; k < 4; ++k)
            red4[k] += __shfl_xor_sync(0xffffffffu, red4[k], o);
    const float kpr = red4[0], kpi = red4[1];
    const float taur = red4[2], taui = red4[3];

    const float wr0 = 1.f + del * kpr, wi0 = del * kpi;
    const float iw = 1.f / (wr0 * wr0 + wi0 * wi0);
    const float gar = del * wr0 * iw, gai = -del * wi0 * iw;
    const float dkr = del * kpr, dki = del * kpi;
    const float alr = del - (gar * dkr - gai * dki);
    const float ali = -(gar * dki + gai * dkr);

    #pragma unroll
    for (int s = 0; s < 2; ++s) {
        const float gr2 = pr[s] * er[s] + pi[s] * ei[s];
        const float gi2 = pr[s] * ei[s] - pi[s] * er[s];
        ur_[s] = alr * pr[s] + ali * pi[s] + gar * gr2 - gai * gi2;
        ui_[s] = -alr * pi[s] + ali * pr[s] + gar * gi2 + gai * gr2;
    }

    float xr0[2], xi0[2];
    {
        const float gtr = gar * taur - gai * taui;
        const float gti = gar * taui + gai * taur;
        #pragma unroll
        for (int s = 0; s < 2; ++s) {
            xr0[s] = mmr[s] - (gtr * qr[s] - gti * qi[s]);
            xi0[s] = mmi[s] - (gtr * qi[s] + gti * qr[s]);
        }
    }

    float qer[T][2], qei[T][2], uer[T][2], uei[T][2], cer[T][2], cei[T][2];
    float e8r[2], e8i[2];
    {
        float emr[2] = {1.f, 1.f}, emi[2] = {0.f, 0.f};
        #pragma unroll
        for (int m = 0; m < T; ++m) {
            #pragma unroll
            for (int s = 0; s < 2; ++s) {
                qer[m][s] = qr[s] * emr[s] - qi[s] * emi[s];
                qei[m][s] = qr[s] * emi[s] + qi[s] * emr[s];
                uer[m][s] = ur_[s] * emr[s] - ui_[s] * emi[s];
                uei[m][s] = ur_[s] * emi[s] + ui_[s] * emr[s];
                cer[m][s] = c2r[s] * emr[s] - c2i[s] * emi[s];
                cei[m][s] = c2r[s] * emi[s] + c2i[s] * emr[s];
                const float t2 = emr[s] * er[s] - emi[s] * ei[s];
                emi[s] = emr[s] * ei[s] + emi[s] * er[s];
                emr[s] = t2;
            }
        }
        e8r[0] = emr[0]; e8i[0] = emi[0]; e8r[1] = emr[1]; e8i[1] = emi[1];
    }

    float red[4 * (T - 1)];
    #pragma unroll
    for (int m = 0; m < T - 1; ++m) {
        float a = 0.f, b = 0.f, c = 0.f, d = 0.f;
        #pragma unroll
        for (int s = 0; s < 2; ++s) {
            a += ur_[s] * qer[m][s] - ui_[s] * qei[m][s];
            b += ur_[s] * qei[m][s] + ui_[s] * qer[m][s];
            c += c2r[s] * qer[m][s] - c2i[s] * qei[m][s];
            d += c2r[s] * qei[m][s] + c2i[s] * qer[m][s];
        }
        red[4 * m] = a; red[4 * m + 1] = b; red[4 * m + 2] = c; red[4 * m + 3] = d;
    }
    #pragma unroll
    for (int o = 16; o; o >>= 1)
        #pragma unroll
        for (int k = 0; k < 4 * (T - 1); ++k)
            red[k] += __shfl_xor_sync(0xffffffffu, red[k], o);

    float nur[T - 1], nui[T - 1], etr[T - 1], eti[T - 1];
    #pragma unroll
    for (int m = 0; m < T - 1; ++m) {
        nur[m] = red[4 * m];     nui[m] = red[4 * m + 1];
        etr[m] = red[4 * m + 2]; eti[m] = red[4 * m + 3];
    }

    float btr[T], bti[T];
    btr[0] = 1.f; bti[0] = 0.f;
    #pragma unroll
    for (int m = 1; m < T; ++m) {
        float a = 0.f, b = 0.f;
        #pragma unroll
        for (int j = 0; j < m; ++j) {
            a -= nur[m - 1 - j] * btr[j] - nui[m - 1 - j] * bti[j];
            b -= nur[m - 1 - j] * bti[j] + nui[m - 1 - j] * btr[j];
        }
        btr[m] = a; bti[m] = b;
    }
    float wcr[T - 1], wci[T - 1];
    #pragma unroll
    for (int m = 0; m < T - 1; ++m) {
        float a = 0.f, b = 0.f;
        #pragma unroll
        for (int j = 0; j <= m; ++j) {
            a += etr[j] * btr[m - j] - eti[j] * bti[m - j];
            b += etr[j] * bti[m - j] + eti[j] * btr[m - j];
        }
        wcr[m] = a; wci[m] = b;
    }

    float rrr[T][2], rri[T][2];
    #pragma unroll
    for (int i = 0; i < T; ++i) {
        #pragma unroll
        for (int s = 0; s < 2; ++s) { rrr[i][s] = 0.f; rri[i][s] = 0.f; }
        #pragma unroll
        for (int j = i; j < T; ++j) {
            const float br2 = btr[j - i], bi2 = bti[j - i];
            #pragma unroll
            for (int s = 0; s < 2; ++s) {
                rrr[i][s] += br2 * qer[T - 1 - j][s] - bi2 * qei[T - 1 - j][s];
                rri[i][s] += br2 * qei[T - 1 - j][s] + bi2 * qer[T - 1 - j][s];
            }
        }
    }

    const u64 NEG1 = pk(-1.f, -1.f);
    const u64 ZERO = pk(0.f, 0.f);

    float* __restrict__ o_ptr = out + (long)h * L;
    const int NB = L / T;               // blocks (assumes L % T == 0 for main loop)
    const int Lb = NB * T;

    float* const spmu = &s_mu_part[hloc][0];
    float* const spk  = &s_k_part[hloc][0];

    u64 Xr = pk(xr0[0], xr0[1]);
    u64 Xi = pk(xi0[0], xi0[1]);

    if (role == 0) {
        // ===== state warp =====
        u64 UEr[T], UEi[T], Rr[T], Ri[T];
        #pragma unroll
        for (int m = 0; m < T; ++m) {
            UEr[m] = pk(uer[m][0], uer[m][1]);
            UEi[m] = pk(uei[m][0], uei[m][1]);
            Rr[m]  = pk(rrr[m][0], rrr[m][1]);
            Ri[m]  = pk(rri[m][0], rri[m][1]);
        }
        const u64 E8r = pk(e8r[0], e8r[1]);
        const u64 E8i = pk(e8i[0], e8i[1]);
        const int rsrow = lane & 15;
        const float4* const rowp = reinterpret_cast<const float4*>(spmu + rsrow * ROWP);

        #pragma unroll 1
        for (int i = 0; i <= NB; ++i) {
            const int par = i & 1;
            if (i < NB) {
                // publish X_i for the output warp
                {
                    float2 a = up(Xr), b = up(Xi);
                    *reinterpret_cast<float4*>(&s_x[hloc][par][lane * 4]) =
                        make_float4(a.x, a.y, b.x, b.y);
                }
                const u64 XiN = f2mul(Xi, NEG1);
                // mu dots -> scatter rows m (mur), 8+m (mui)
                #pragma unroll
                for (int m = 0; m < T; ++m) {
                    float2 a = up(f2fma(UEi[m], XiN, f2mul(UEr[m], Xr)));
                    float2 b = up(f2fma(UEi[m], Xr,  f2mul(UEr[m], Xi)));
                    spmu[m * ROWP + lane]       = a.x + a.y;
                    spmu[(8 + m) * ROWP + lane] = b.x + b.y;
                }
                __syncwarp();
                // rowsum (lanes 16-31 duplicate rows 0-15)
                float rs;
                {
                    float4 v0 = rowp[0], v1 = rowp[1], v2 = rowp[2], v3 = rowp[3];
                    float4 v4 = rowp[4], v5 = rowp[5], v6 = rowp[6], v7 = rowp[7];
                    float4 t0 = make_float4(v0.x + v4.x, v0.y + v4.y, v0.z + v4.z, v0.w + v4.w);
                    float4 t1 = make_float4(v1.x + v5.x, v1.y + v5.y, v1.z + v5.z, v1.w + v5.w);
                    float4 t2 = make_float4(v2.x + v6.x, v2.y + v6.y, v2.z + v6.z, v2.w + v6.w);
                    float4 t3 = make_float4(v3.x + v7.x, v3.y + v7.y, v3.z + v7.z, v3.w + v7.w);
                    float4 u0 = make_float4(t0.x + t2.x, t0.y + t2.y, t0.z + t2.z, t0.w + t2.w);
                    float4 u1 = make_float4(t1.x + t3.x, t1.y + t3.y, t1.z + t3.z, t1.w + t3.w);
                    float4 ww = make_float4(u0.x + u1.x, u0.y + u1.y, u0.z + u1.z, u0.w + u1.w);
                    rs = (ww.x + ww.y) + (ww.z + ww.w);
                }
                s_mu[hloc][par][rsrow] = rs;   // duplicate same-value writes OK
                __syncwarp();
                // broadcast mu
                const float4 m0 = *reinterpret_cast<const float4*>(&s_mu[hloc][par][0]);
                const float4 m1 = *reinterpret_cast<const float4*>(&s_mu[hloc][par][4]);
                const float4 n0 = *reinterpret_cast<const float4*>(&s_mu[hloc][par][8]);
                const float4 n1 = *reinterpret_cast<const float4*>(&s_mu[hloc][par][12]);
                const float mur[T] = {m0.x, m0.y, m0.z, m0.w, m1.x, m1.y, m1.z, m1.w};
                const float mui[T] = {n0.x, n0.y, n0.z, n0.w, n1.x, n1.y, n1.z, n1.w};
                // state update (two chains)
                u64 A0 = f2fma(E8i, XiN, f2mul(E8r, Xr));
                u64 B0 = f2fma(E8i, Xr,  f2mul(E8r, Xi));
                u64 A1 = ZERO, B1 = ZERO;
                #pragma unroll
                for (int k = 0; k < T; k += 2) {
                    const u64 a0 = pk(-mur[k], -mur[k]);
                    const u64 b0 = pk(mui[k], mui[k]);
                    const u64 c0 = pk(-mui[k], -mui[k]);
                    A0 = f2fma(a0, Rr[k], f2fma(b0, Ri[k], A0));
                    B0 = f2fma(a0, Ri[k], f2fma(c0, Rr[k], B0));
                    const u64 a1 = pk(-mur[k + 1], -mur[k + 1]);
                    const u64 b1 = pk(mui[k + 1], mui[k + 1]);
                    const u64 c1 = pk(-mui[k + 1], -mui[k + 1]);
                    A1 = f2fma(a1, Rr[k + 1], f2fma(b1, Ri[k + 1], A1));
                    B1 = f2fma(a1, Ri[k + 1], f2fma(c1, Rr[k + 1], B1));
                }
                Xr = f2add(A0, A1);
                Xi = f2add(B0, B1);
            }
            __syncthreads();
        }
    } else {
        // ===== output warp (one block behind) =====
        u64 CEr[T], CEi[T];
        #pragma unroll
        for (int m = 0; m < T; ++m) {
            CEr[m] = pk(cer[m][0], cer[m][1]);
            CEi[m] = pk(cei[m][0], cei[m][1]);
        }
        const int mo = lane & 7;
        float mwr[T - 1], mwi[T - 1];
        int mix0[T - 1], mix1[T - 1];
        #pragma unroll
        for (int d = 0; d < T - 1; ++d) {
            const bool act = d < mo;
            const int idx = act ? (mo - 1 - d) : 0;
            mwr[d] = act ? -wcr[d] : 0.f;
            mwi[d] = act ? wci[d] : 0.f;
            mix0[d] = idx;
            mix1[d] = 8 + idx;
        }
        const bool do_store = (lane < 8);
        const float4* const rowp = reinterpret_cast<const float4*>(spk + mo * ROWP);

        #pragma unroll 1
        for (int i = 0; i <= NB; ++i) {
            if (i > 0) {
                const int pprev = (i - 1) & 1;
                const float4 xv = *reinterpret_cast<const float4*>(&s_x[hloc][pprev][lane * 4]);
                const u64 Xr2 = pk(xv.x, xv.y);
                const u64 Xi2 = pk(xv.z, xv.w);
                const u64 XiN2 = f2mul(Xi2, NEG1);
                #pragma unroll
                for (int m = 0; m < T; ++m) {
                    float2 c = up(f2fma(CEi[m], XiN2, f2mul(CEr[m], Xr2)));
                    spk[m * ROWP + lane] = c.x + c.y;
                }
                __syncwarp();
                float kv;
                {
                    float4 v0 = rowp[0], v1 = rowp[1], v2 = rowp[2], v3 = rowp[3];
                    float4 v4 = rowp[4], v5 = rowp[5], v6 = rowp[6], v7 = rowp[7];
                    float4 t0 = make_float4(v0.x + v4.x, v0.y + v4.y, v0.z + v4.z, v0.w + v4.w);
                    float4 t1 = make_float4(v1.x + v5.x, v1.y + v5.y, v1.z + v5.z, v1.w + v5.w);
                    float4 t2 = make_float4(v2.x + v6.x, v2.y + v6.y, v2.z + v6.z, v2.w + v6.w);
                    float4 t3 = make_float4(v3.x + v7.x, v3.y + v7.y, v3.z + v7.z, v3.w + v7.w);
                    float4 u0 = make_float4(t0.x + t2.x, t0.y + t2.y, t0.z + t2.z, t0.w + t2.w);
                    float4 u1 = make_float4(t1.x + t3.x, t1.y + t3.y, t1.z + t3.z, t1.w + t3.w);
                    float4 ww = make_float4(u0.x + u1.x, u0.y + u1.y, u0.z + u1.z, u0.w + u1.w);
                    kv = (ww.x + ww.y) + (ww.z + ww.w);
                }
                const float* mb = &s_mu[hloc][pprev][0];
                #pragma unroll
                for (int d = 0; d < T - 1; ++d)
                    kv = fmaf(mwr[d], mb[mix0[d]], fmaf(mwi[d], mb[mix1[d]], kv));
                if (do_store) o_ptr[(i - 1) * T + mo] = kv;
            }
            __syncthreads();
        }
    }

    // remainder (L not divisible by T): state warp finishes scalar steps
    if (role == 0) {
        for (int l = Lb; l < L; ++l) {
            float2 xr2 = up(Xr), xi2 = up(Xi);
            float xrr[2] = {xr2.x, xr2.y}, xii[2] = {xi2.x, xi2.y};
            float sr2 = 0.f, si2 = 0.f, kv = 0.f;
            #pragma unroll
            for (int s = 0; s < 2; ++s) {
                sr2 += ur_[s] * xrr[s] - ui_[s] * xii[s];
                si2 += ur_[s] * xii[s] + ui_[s] * xrr[s];
                kv  += c2r[s] * xrr[s] - c2i[s] * xii[s];
            }
            sr2 = wsum(sr2); si2 = wsum(si2); kv = wsum(kv);
            if (lane == 0) o_ptr[l] = kv;
            float nxr[2], nxi[2];
            #pragma unroll
            for (int s = 0; s < 2; ++s) {
                nxr[s] = er[s] * xrr[s] - ei[s] * xii[s] - (sr2 * qr[s] - si2 * qi[s]);
                nxi[s] = er[s] * xii[s] + ei[s] * xrr[s] - (sr2 * qi[s] + si2 * qr[s]);
            }
            Xr = pk(nxr[0], nxr[1]); Xi = pk(nxi[0], nxi[1]);
        }
    }
}

extern "C" void kernel_launch(void* const* d_in, const int* in_sizes, int n_in,
                              void* d_out, int out_size) {
    const float* Ar = (const float*)d_in[0];
    const float* Ai = (const float*)d_in[1];
    const float* Br = (const float*)d_in[2];
    const float* Bi = (const float*)d_in[3];
    const float* Pr = (const float*)d_in[4];
    const float* Pi = (const float*)d_in[5];
    const float* Cr = (const float*)d_in[6];
    const float* Ci = (const float*)d_in[7];
    const float* ld = (const float*)d_in[8];
    float* out = (float*)d_out;

    const int H = in_sizes[8];          // 256
    const int L = out_size / H;         // CH = 1 -> 2048

    const int blocks = (H + 1) / 2;     // 2 heads per CTA, 2 warps per head
    ssm_dplr_kernel<<<blocks, 128>>>(
        Ar, Ai, Br, Bi, Pr, Pi, Cr, Ci, ld, out, H, L);
}